// round 5
// baseline (speedup 1.0000x reference)
#include <cuda_runtime.h>
#include <cuda_bf16.h>
#include <cstdint>

#define NB 32768
#define NK 8192
#define ND 256
#define BETA 0.25f

#define BM 128
#define BN 128
#define KC 32            // features per streamed B chunk
#define NCH 8            // chunks per tile (256/32)
#define NT 64            // code tiles (8192/128)
#define NU (NT * NCH)    // 512 chunk-iterations
#define CAP 32
#define EPSF 8e-4f

// ---- shared memory layout (u32 words) ----
#define SA_W 132                       // A row stride: 264 bf16 (256 + 8 pad)
#define SB_W 20                        // B row stride: 40 bf16 (32 + 8 pad)
#define A_WORDS (BM * SA_W)            // 16896
#define B_WORDS (BM * SB_W)            // 2560 per buffer
#define OFF_A  0
#define OFF_B  (A_WORDS)
#define OFF_ZN (OFF_B + 2 * B_WORDS)
#define OFF_EN (OFF_ZN + 128)
#define OFF_RB (OFF_EN + 128)
#define OFF_RC (OFF_RB + 128)
#define OFF_RL (OFF_RC + 128)
#define SMEM_WORDS (OFF_RL + BM * CAP)
#define SMEM_BYTES (SMEM_WORDS * 4)    // 106496 B

// ---- global scratch ----
__device__ float g_znorm[NB];
__device__ float g_enorm[NK];
__device__ int   g_idx[NB];
__device__ float g_partial[NB];
__device__ int   g_cand[(size_t)NB * CAP];
__device__ int   g_cnt[NB];

__device__ __forceinline__ void mma_bf16(float* c, const uint32_t* a, const uint32_t* b) {
    asm volatile("mma.sync.aligned.m16n8k16.row.col.f32.bf16.bf16.f32 "
                 "{%0,%1,%2,%3}, {%4,%5,%6,%7}, {%8,%9}, {%0,%1,%2,%3};"
                 : "+f"(c[0]), "+f"(c[1]), "+f"(c[2]), "+f"(c[3])
                 : "r"(a[0]), "r"(a[1]), "r"(a[2]), "r"(a[3]), "r"(b[0]), "r"(b[1]));
}
__device__ __forceinline__ uint32_t pack_bf16(float x, float y) {
    __nv_bfloat162 p = __floats2bfloat162_rn(x, y);   // .x = low half = first k
    return *(uint32_t*)&p;
}

// ---------------------------------------------------------------------------
// Row squared-norms (exact fp32).
// ---------------------------------------------------------------------------
__global__ void vq_rownorm_kernel(const float* __restrict__ x, int nrows, int which) {
    int gw   = (int)((blockIdx.x * (unsigned)blockDim.x + threadIdx.x) >> 5);
    int lane = threadIdx.x & 31;
    if (gw >= nrows) return;
    const float4* row = (const float4*)(x + (size_t)gw * ND);
    float4 v0 = row[lane];
    float4 v1 = row[lane + 32];
    float s = v0.x * v0.x + v0.y * v0.y + v0.z * v0.z + v0.w * v0.w
            + v1.x * v1.x + v1.y * v1.y + v1.z * v1.z + v1.w * v1.w;
#pragma unroll
    for (int off = 16; off > 0; off >>= 1) s += __shfl_down_sync(0xffffffffu, s, off);
    if (lane == 0) { if (which) g_enorm[gw] = s; else g_znorm[gw] = s; }
}

// ---------------------------------------------------------------------------
// bf16 mma.sync distance GEMM + fused eps-window candidate filter.
// ---------------------------------------------------------------------------
__global__ __launch_bounds__(256, 1)
void vq_mma_kernel(const float* __restrict__ z, const float* __restrict__ e) {
    extern __shared__ __align__(16) uint32_t sm[];
    uint32_t* As = sm + OFF_A;
    float*    zn = (float*)(sm + OFF_ZN);
    float*    en = (float*)(sm + OFF_EN);
    int*      rb = (int*)(sm + OFF_RB);
    int*      rc = (int*)(sm + OFF_RC);
    int*      rl = (int*)(sm + OFF_RL);

    const int tid  = threadIdx.x;
    const int wid  = tid >> 5;
    const int lane = tid & 31;
    const int g    = lane >> 2;        // fragment group (row/col within 8)
    const int tg   = lane & 3;         // thread-in-group
    const int wm   = wid & 1;          // warp M position (0/1 -> rows +0/+64)
    const int wn   = wid >> 1;         // warp N position (0..3 -> cols +32*wn)
    const int m0   = blockIdx.x * BM;

    // ---- prologue: A (z rows) -> bf16 smem, norms, filter state ----
#pragma unroll
    for (int i = 0; i < 32; i++) {
        int j = tid + 256 * i;
        int r = j >> 6, fi = j & 63;
        float4 v = *(const float4*)&z[(size_t)(m0 + r) * ND + fi * 4];
        As[r * SA_W + fi * 2]     = pack_bf16(v.x, v.y);
        As[r * SA_W + fi * 2 + 1] = pack_bf16(v.z, v.w);
    }
    if (tid < 128) {
        zn[tid] = g_znorm[m0 + tid];
        en[tid] = g_enorm[tid];          // tile 0
        rb[tid] = 0x7F800000;            // +inf bits (positive-float int order)
        rc[tid] = 0;
    }
    // chunk 0 of tile 0 into buffer 0
    {
        uint32_t* Bs = sm + OFF_B;
#pragma unroll
        for (int i = 0; i < 4; i++) {
            int j = tid + 256 * i;
            int code = j >> 3, fi = j & 7;
            float4 v = *(const float4*)&e[(size_t)code * ND + fi * 4];
            Bs[code * SB_W + fi * 2]     = pack_bf16(v.x, v.y);
            Bs[code * SB_W + fi * 2 + 1] = pack_bf16(v.z, v.w);
        }
    }
    __syncthreads();

    float acc[4][4][4];
#pragma unroll
    for (int a = 0; a < 4; a++)
#pragma unroll
        for (int b = 0; b < 4; b++)
#pragma unroll
            for (int q = 0; q < 4; q++) acc[a][b][q] = 0.0f;

    float4 bv[4];
    for (int u = 0; u < NU; u++) {
        const int t = u >> 3, c = u & 7;

        // stage next chunk gmem -> regs
        if (u + 1 < NU) {
            int tn = (u + 1) >> 3, cn = (u + 1) & 7;
            const float* eb = e + (size_t)tn * BN * ND + cn * KC;
#pragma unroll
            for (int i = 0; i < 4; i++) {
                int j = tid + 256 * i;
                bv[i] = *(const float4*)&eb[(size_t)(j >> 3) * ND + (j & 7) * 4];
            }
        }

        // compute chunk c from buffer u&1
        {
            const uint32_t* Bb = sm + OFF_B + (u & 1) * B_WORDS;
            const int wbase = c * 16;
#pragma unroll
            for (int ks = 0; ks < 2; ks++) {
                uint32_t afr[4][4];
#pragma unroll
                for (int mt = 0; mt < 4; mt++) {
                    int r0 = wm * 64 + mt * 16 + g;
                    int wa = wbase + ks * 8 + tg;
                    afr[mt][0] = As[r0 * SA_W + wa];
                    afr[mt][1] = As[(r0 + 8) * SA_W + wa];
                    afr[mt][2] = As[r0 * SA_W + wa + 4];
                    afr[mt][3] = As[(r0 + 8) * SA_W + wa + 4];
                }
                uint32_t bfr[4][2];
#pragma unroll
                for (int nt = 0; nt < 4; nt++) {
                    int cl = wn * 32 + nt * 8 + g;
                    bfr[nt][0] = Bb[cl * SB_W + ks * 8 + tg];
                    bfr[nt][1] = Bb[cl * SB_W + ks * 8 + tg + 4];
                }
#pragma unroll
                for (int mt = 0; mt < 4; mt++)
#pragma unroll
                    for (int nt = 0; nt < 4; nt++)
                        mma_bf16(acc[mt][nt], afr[mt], bfr[nt]);
            }
        }

        // store staged chunk to the other buffer
        if (u + 1 < NU) {
            uint32_t* Bs = sm + OFF_B + ((u + 1) & 1) * B_WORDS;
#pragma unroll
            for (int i = 0; i < 4; i++) {
                int j = tid + 256 * i;
                int code = j >> 3, fi = j & 7;
                Bs[code * SB_W + fi * 2]     = pack_bf16(bv[i].x, bv[i].y);
                Bs[code * SB_W + fi * 2 + 1] = pack_bf16(bv[i].z, bv[i].w);
            }
        }
        // refresh enorm for this tile's epilogue at its first chunk (t>0)
        if (c == 0 && t > 0 && tid < 128) en[tid] = g_enorm[t * BN + tid];

        // ---- tile epilogue ----
        if (c == 7) {
            float env[8], znv[8];
#pragma unroll
            for (int nt = 0; nt < 4; nt++)
#pragma unroll
                for (int jj = 0; jj < 2; jj++)
                    env[nt * 2 + jj] = en[wn * 32 + nt * 8 + 2 * tg + jj];
#pragma unroll
            for (int mt = 0; mt < 4; mt++)
#pragma unroll
                for (int hf = 0; hf < 2; hf++)
                    znv[mt * 2 + hf] = zn[wm * 64 + mt * 16 + hf * 8 + g];

            // pass 1: per-row tile min -> atomicMin(rowbest)
#pragma unroll
            for (int mt = 0; mt < 4; mt++)
#pragma unroll
                for (int hf = 0; hf < 2; hf++) {
                    float mn = 3.4028235e38f;
#pragma unroll
                    for (int nt = 0; nt < 4; nt++)
#pragma unroll
                        for (int jj = 0; jj < 2; jj++)
                            mn = fminf(mn, fmaf(-2.0f, acc[mt][nt][hf * 2 + jj],
                                                znv[mt * 2 + hf] + env[nt * 2 + jj]));
                    mn = fminf(mn, __shfl_xor_sync(0xffffffffu, mn, 1));
                    mn = fminf(mn, __shfl_xor_sync(0xffffffffu, mn, 2));
                    if (tg == 0)
                        atomicMin(&rb[wm * 64 + mt * 16 + hf * 8 + g], __float_as_int(mn));
                }
            __syncthreads();
            // pass 2: append candidates within eps window
#pragma unroll
            for (int mt = 0; mt < 4; mt++)
#pragma unroll
                for (int hf = 0; hf < 2; hf++) {
                    int row = wm * 64 + mt * 16 + hf * 8 + g;
                    float lim = __int_as_float(rb[row]) + EPSF;
#pragma unroll
                    for (int nt = 0; nt < 4; nt++)
#pragma unroll
                        for (int jj = 0; jj < 2; jj++) {
                            float dist = fmaf(-2.0f, acc[mt][nt][hf * 2 + jj],
                                              znv[mt * 2 + hf] + env[nt * 2 + jj]);
                            if (dist <= lim) {
                                int p = atomicAdd(&rc[row], 1);
                                if (p < CAP)
                                    rl[row * CAP + p] = t * BN + wn * 32 + nt * 8 + 2 * tg + jj;
                            }
                        }
                    // reset accumulators for next tile
#pragma unroll
                    for (int nt = 0; nt < 4; nt++)
#pragma unroll
                        for (int jj = 0; jj < 2; jj++) acc[mt][nt][hf * 2 + jj] = 0.0f;
                }
        }
        __syncthreads();
    }

    if (tid < 128) {
        int cnt = rc[tid];
        g_cnt[m0 + tid] = (cnt > CAP) ? -1 : cnt;
        int n = cnt > CAP ? CAP : cnt;
        for (int q = 0; q < n; q++) g_cand[(size_t)(m0 + tid) * CAP + q] = rl[tid * CAP + q];
    }
}

// ---------------------------------------------------------------------------
// Exact fp32 recheck: thread per row, sequential-fma dot (round-2-proven
// accumulation order). Strict '<' ascending-k = jnp.argmin tie-break.
// ---------------------------------------------------------------------------
__global__ void vq_recheck_kernel(const float* __restrict__ z, const float* __restrict__ e) {
    int row = blockIdx.x * 256 + threadIdx.x;
    int n = g_cnt[row];
    int bi;
    if (n == 1) {
        bi = g_cand[(size_t)row * CAP];
    } else {
        float a = g_znorm[row];
        float best = 3.4028235e38f;
        bi = 0;
        int m = (n < 0) ? NK : n;
        const float* zr = z + (size_t)row * ND;
        for (int j = 0; j < m; j++) {
            int k = (n < 0) ? j : g_cand[(size_t)row * CAP + j];
            const float* er = e + (size_t)k * ND;
            float dot = 0.0f;
            for (int d = 0; d < ND; d++) dot = fmaf(zr[d], er[d], dot);
            float dist = fmaf(-2.0f, dot, a + g_enorm[k]);
            if (j == 0 || dist < best || (dist == best && k < bi)) { best = dist; bi = k; }
        }
    }
    g_idx[row] = bi;
}

// ---------------------------------------------------------------------------
// Gather + straight-through output + per-row loss partial + index output.
// ---------------------------------------------------------------------------
__global__ void vq_gather_kernel(const float* __restrict__ z,
                                 const float* __restrict__ e,
                                 float* __restrict__ out) {
    int row = blockIdx.x;
    int t   = threadIdx.x;
    int idx = g_idx[row];
    float zv = z[(size_t)row * ND + t];
    float ev = e[(size_t)idx * ND + t];
    float d  = ev - zv;
    out[(size_t)row * ND + t] = zv + d;
    float sq = d * d;
#pragma unroll
    for (int off = 16; off > 0; off >>= 1) sq += __shfl_down_sync(0xffffffffu, sq, off);
    __shared__ float red[8];
    if ((t & 31) == 0) red[t >> 5] = sq;
    __syncthreads();
    if (t < 8) {
        float v = red[t];
#pragma unroll
        for (int off = 4; off > 0; off >>= 1) v += __shfl_down_sync(0xffu, v, off);
        if (t == 0) g_partial[row] = v;
    }
    if (t == 0) out[(size_t)NB * ND + 2 + row] = (float)idx;
}

__global__ void vq_finalize_kernel(float* __restrict__ out) {
    int t = threadIdx.x;
    float s = 0.0f;
    for (int i = t; i < NB; i += 256) s += g_partial[i];
#pragma unroll
    for (int off = 16; off > 0; off >>= 1) s += __shfl_down_sync(0xffffffffu, s, off);
    __shared__ float red[8];
    if ((t & 31) == 0) red[t >> 5] = s;
    __syncthreads();
    if (t == 0) {
        float tot = 0.0f;
#pragma unroll
        for (int w = 0; w < 8; w++) tot += red[w];
        float l = BETA * (tot / (float)((size_t)NB * ND));
        out[(size_t)NB * ND]     = l;
        out[(size_t)NB * ND + 1] = l;
    }
}

extern "C" void kernel_launch(void* const* d_in, const int* in_sizes, int n_in,
                              void* d_out, int out_size) {
    const float* z = (const float*)d_in[0];
    const float* e = (const float*)d_in[1];
    float* out = (float*)d_out;

    cudaFuncSetAttribute(vq_mma_kernel, cudaFuncAttributeMaxDynamicSharedMemorySize, SMEM_BYTES);

    vq_rownorm_kernel<<<(NB * 32 + 255) / 256, 256>>>(z, NB, 0);
    vq_rownorm_kernel<<<(NK * 32 + 255) / 256, 256>>>(e, NK, 1);
    vq_mma_kernel<<<NB / BM, 256, SMEM_BYTES>>>(z, e);
    vq_recheck_kernel<<<NB / 256, 256>>>(z, e);
    vq_gather_kernel<<<NB, 256>>>(z, e, out);
    vq_finalize_kernel<<<1, 256>>>(out);
}

// round 6
// speedup vs baseline: 16.5840x; 16.5840x over previous
#include <cuda_runtime.h>
#include <cstdint>

#define NB 32768
#define NK 8192
#define ND 256
#define BETA 0.25f

#define BM 128
#define BN 128
#define BD 32
#define SPAD 4
#define SLD (BM + SPAD)

typedef unsigned long long u64;

// Scratch (no allocations allowed in kernel_launch).
__device__ float g_znorm[NB];
__device__ float g_enorm[NK];
__device__ int   g_idx[NB];
__device__ float g_partial[NB];

__device__ __forceinline__ u64 pack2(float lo, float hi) {
    u64 r; asm("mov.b64 %0, {%1, %2};" : "=l"(r) : "f"(lo), "f"(hi)); return r;
}
__device__ __forceinline__ void unpack2(float& lo, float& hi, u64 v) {
    asm("mov.b64 {%0, %1}, %2;" : "=f"(lo), "=f"(hi) : "l"(v));
}
__device__ __forceinline__ void fma2(u64& d, u64 a, u64 b) {
    asm("fma.rn.f32x2 %0, %1, %2, %0;" : "+l"(d) : "l"(a), "l"(b));
}

// ---------------------------------------------------------------------------
// Row squared-norms: one warp per row, vectorized float4 loads.
// ---------------------------------------------------------------------------
__global__ void vq_rownorm_kernel(const float* __restrict__ x, int nrows, int which) {
    int gw   = (int)((blockIdx.x * (unsigned)blockDim.x + threadIdx.x) >> 5);
    int lane = threadIdx.x & 31;
    if (gw >= nrows) return;
    const float4* row = (const float4*)(x + (size_t)gw * ND);
    float4 v0 = row[lane];
    float4 v1 = row[lane + 32];
    float s = v0.x * v0.x + v0.y * v0.y + v0.z * v0.z + v0.w * v0.w
            + v1.x * v1.x + v1.y * v1.y + v1.z * v1.z + v1.w * v1.w;
#pragma unroll
    for (int off = 16; off > 0; off >>= 1)
        s += __shfl_down_sync(0xffffffffu, s, off);
    if (lane == 0) {
        if (which) g_enorm[gw] = s;
        else       g_znorm[gw] = s;
    }
}

// ---------------------------------------------------------------------------
// Fused distance-GEMM + running argmin, inner product via packed fma.rn.f32x2
// (2 IEEE fp32 FMAs per issue slot; per-lane arithmetic bit-identical to the
// scalar round-2 kernel). dist = fmaf(-2, dot, ||z||^2 + ||e||^2) matches the
// reference expression tree. Ascending-k strict '<' = jnp.argmin tie-break.
// ---------------------------------------------------------------------------
__global__ __launch_bounds__(256, 2)
void vq_argmin_kernel(const float* __restrict__ z, const float* __restrict__ e) {
    __shared__ float smem[2 * BD * SLD + BN];   // zs | es | bsh  (~34 KB)
    float* zs  = smem;
    float* es  = smem + BD * SLD;
    float* bsh = smem + 2 * BD * SLD;

    int tid = threadIdx.x;
    int tx  = tid & 15;   // code sub-tile (8 codes)
    int ty  = tid >> 4;   // row sub-tile  (8 rows)
    int m0  = blockIdx.x * BM;

    float best[8];
    int   bidx[8];
#pragma unroll
    for (int i = 0; i < 8; i++) { best[i] = 3.4028235e38f; bidx[i] = 0; }

    float arow[8];
#pragma unroll
    for (int i = 0; i < 8; i++) arow[i] = g_znorm[m0 + ty * 8 + i];

    const int lc = tid & 31;   // d-column within chunk
    const int lr = tid >> 5;   // base row for tile loads

    for (int k0 = 0; k0 < NK; k0 += BN) {
        if (tid < BN) bsh[tid] = g_enorm[k0 + tid];

        u64 acc2[8][4];
#pragma unroll
        for (int i = 0; i < 8; i++)
#pragma unroll
            for (int q = 0; q < 4; q++) acc2[i][q] = 0ULL;

        for (int d0 = 0; d0 < ND; d0 += BD) {
            __syncthreads();   // protect smem tiles (and bsh on first pass)
#pragma unroll
            for (int rr = 0; rr < BM; rr += 8) {
                zs[lc * SLD + lr + rr] = z[(size_t)(m0 + lr + rr) * ND + d0 + lc];
                es[lc * SLD + lr + rr] = e[(size_t)(k0 + lr + rr) * ND + d0 + lc];
            }
            __syncthreads();
#pragma unroll 8
            for (int dd = 0; dd < BD; dd++) {
                float4 za0 = *(const float4*)&zs[dd * SLD + ty * 8];
                float4 za1 = *(const float4*)&zs[dd * SLD + ty * 8 + 4];
                float4 eb0 = *(const float4*)&es[dd * SLD + tx * 8];
                float4 eb1 = *(const float4*)&es[dd * SLD + tx * 8 + 4];
                u64 eb2[4];
                eb2[0] = pack2(eb0.x, eb0.y);
                eb2[1] = pack2(eb0.z, eb0.w);
                eb2[2] = pack2(eb1.x, eb1.y);
                eb2[3] = pack2(eb1.z, eb1.w);
                float za[8] = {za0.x, za0.y, za0.z, za0.w, za1.x, za1.y, za1.z, za1.w};
#pragma unroll
                for (int i = 0; i < 8; i++) {
                    u64 za2 = pack2(za[i], za[i]);
#pragma unroll
                    for (int q = 0; q < 4; q++)
                        fma2(acc2[i][q], za2, eb2[q]);
                }
            }
        }

        // Epilogue: distances + running argmin for this code tile.
#pragma unroll
        for (int i = 0; i < 8; i++) {
#pragma unroll
            for (int q = 0; q < 4; q++) {
                float dlo, dhi;
                unpack2(dlo, dhi, acc2[i][q]);
                float dv0 = fmaf(-2.0f, dlo, arow[i] + bsh[tx * 8 + 2 * q]);
                float dv1 = fmaf(-2.0f, dhi, arow[i] + bsh[tx * 8 + 2 * q + 1]);
                int   kk0 = k0 + tx * 8 + 2 * q;
                if (dv0 < best[i]) { best[i] = dv0; bidx[i] = kk0; }
                if (dv1 < best[i]) { best[i] = dv1; bidx[i] = kk0 + 1; }
            }
        }
        __syncthreads();   // bsh is rewritten at top of next tile
    }

    // Cross-thread reduction: 16 threads (tx) share each of the 128 rows.
    float* rval = smem;                       // BM*16 floats
    int*   ridx = (int*)(smem + BM * 16);     // BM*16 ints
#pragma unroll
    for (int i = 0; i < 8; i++) {
        rval[(ty * 8 + i) * 16 + tx] = best[i];
        ridx[(ty * 8 + i) * 16 + tx] = bidx[i];
    }
    __syncthreads();
    if (tid < BM) {
        float bv = rval[tid * 16];
        int   bi = ridx[tid * 16];
#pragma unroll
        for (int t = 1; t < 16; t++) {
            float v  = rval[tid * 16 + t];
            int   ix = ridx[tid * 16 + t];
            if (v < bv || (v == bv && ix < bi)) { bv = v; bi = ix; }
        }
        g_idx[m0 + tid] = bi;
    }
}

// ---------------------------------------------------------------------------
// Gather + straight-through output + per-row loss partial + index output.
// ---------------------------------------------------------------------------
__global__ void vq_gather_kernel(const float* __restrict__ z,
                                 const float* __restrict__ e,
                                 float* __restrict__ out) {
    int row = blockIdx.x;
    int t   = threadIdx.x;
    int idx = g_idx[row];

    float zv = z[(size_t)row * ND + t];
    float ev = e[(size_t)idx * ND + t];
    float d  = ev - zv;                         // fl(z_q - z)
    out[(size_t)row * ND + t] = zv + d;         // z + stopgrad(z_q - z)
    float sq = d * d;

#pragma unroll
    for (int off = 16; off > 0; off >>= 1)
        sq += __shfl_down_sync(0xffffffffu, sq, off);

    __shared__ float red[8];
    if ((t & 31) == 0) red[t >> 5] = sq;
    __syncthreads();
    if (t < 8) {
        float v = red[t];
#pragma unroll
        for (int off = 4; off > 0; off >>= 1)
            v += __shfl_down_sync(0xffu, v, off);
        if (t == 0) g_partial[row] = v;
    }
    if (t == 0) out[(size_t)NB * ND + 2 + row] = (float)idx;
}

// ---------------------------------------------------------------------------
// Final scalar reduction: sums per-row loss partials, writes both losses.
// ---------------------------------------------------------------------------
__global__ void vq_finalize_kernel(float* __restrict__ out) {
    int t = threadIdx.x;
    float s = 0.0f;
    for (int i = t; i < NB; i += 256) s += g_partial[i];
#pragma unroll
    for (int off = 16; off > 0; off >>= 1)
        s += __shfl_down_sync(0xffffffffu, s, off);
    __shared__ float red[8];
    if ((t & 31) == 0) red[t >> 5] = s;
    __syncthreads();
    if (t == 0) {
        float tot = 0.0f;
#pragma unroll
        for (int w = 0; w < 8; w++) tot += red[w];
        float l = BETA * (tot / (float)((size_t)NB * ND));
        out[(size_t)NB * ND]     = l;   // vq_loss
        out[(size_t)NB * ND + 1] = l;   // commit (numerically identical)
    }
}

extern "C" void kernel_launch(void* const* d_in, const int* in_sizes, int n_in,
                              void* d_out, int out_size) {
    const float* z = (const float*)d_in[0];
    const float* e = (const float*)d_in[1];
    float* out = (float*)d_out;

    vq_rownorm_kernel<<<(NB * 32 + 255) / 256, 256>>>(z, NB, 0);
    vq_rownorm_kernel<<<(NK * 32 + 255) / 256, 256>>>(e, NK, 1);
    vq_argmin_kernel<<<NB / BM, 256>>>(z, e);
    vq_gather_kernel<<<NB, 256>>>(z, e, out);
    vq_finalize_kernel<<<1, 256>>>(out);
}